// round 10
// baseline (speedup 1.0000x reference)
#include <cuda_runtime.h>
#include <cuda_bf16.h>
#include <cstdint>

#define N_NODES 50000
#define N_EDGES 800000
#define D_IN    256
#define D_HID   256
#define D_OUT   128
#define GRID_M  391            // ceil(50000/128)
#define HISTB   3125           // ceil(800000/256)
#define YSPB    12500          // 50000*256/4 float4 / 256 threads
#define G1B     (2 * GRID_M)   // 782 GEMM1 blocks
#define EPB     1024           // edges scattered per GEMM1 block

// ---------------- scratch ------------------------------------------------------
__device__ float g_H1[(size_t)N_NODES * D_HID];
__device__ __nv_bfloat16 g_H2h[(size_t)N_NODES * D_HID];
__device__ __nv_bfloat16 g_H2l[(size_t)N_NODES * D_HID];
__device__ float g_H3[(size_t)N_NODES * D_OUT];
__device__ __nv_bfloat16 g_Yh[(size_t)N_NODES * D_IN];
__device__ __nv_bfloat16 g_Yl[(size_t)N_NODES * D_IN];
__device__ __nv_bfloat16 g_W1Th[D_HID * D_IN];
__device__ __nv_bfloat16 g_W1Tl[D_HID * D_IN];
__device__ __nv_bfloat16 g_W2Th[D_OUT * D_HID];
__device__ __nv_bfloat16 g_W2Tl[D_OUT * D_HID];
__device__ int   g_rowptr[N_NODES + 1];
__device__ int   g_cursor[N_NODES];
__device__ int   g_bsum[256];
__device__ int2  g_ecv[N_EDGES];

// ---------------- helpers ------------------------------------------------------
__device__ __forceinline__ void split_f4(float4 f, uint2& hi, uint2& lo) {
    __nv_bfloat162 h01 = __floats2bfloat162_rn(f.x, f.y);
    __nv_bfloat162 h23 = __floats2bfloat162_rn(f.z, f.w);
    float2 g01 = __bfloat1622float2(h01);
    float2 g23 = __bfloat1622float2(h23);
    __nv_bfloat162 l01 = __floats2bfloat162_rn(f.x - g01.x, f.y - g01.y);
    __nv_bfloat162 l23 = __floats2bfloat162_rn(f.z - g23.x, f.w - g23.y);
    hi.x = *(uint32_t*)&h01; hi.y = *(uint32_t*)&h23;
    lo.x = *(uint32_t*)&l01; lo.y = *(uint32_t*)&l23;
}

// ---------------- K1: hist + W splits + Y split --------------------------------
__global__ void k_init_all(const int* __restrict__ erow,
                           const float* __restrict__ W1,
                           const float* __restrict__ W2,
                           const float* __restrict__ Y) {
    int b = blockIdx.x;
    if (b < HISTB) {
        int i = b * 256 + threadIdx.x;
        if (i < N_EDGES) atomicAdd(&g_rowptr[erow[i] + 1], 1);
        return;
    }
    b -= HISTB;
    if (b < 256) {               // W1 [256][256] -> T split
        int i = b * 256 + threadIdx.x;
        int r = i >> 8, c = i & 255;
        float v = W1[i];
        __nv_bfloat16 h = __float2bfloat16(v);
        g_W1Th[(size_t)c * D_IN + r] = h;
        g_W1Tl[(size_t)c * D_IN + r] = __float2bfloat16(v - __bfloat162float(h));
        return;
    }
    b -= 256;
    if (b < 128) {               // W2 [256][128] -> T split
        int i = b * 256 + threadIdx.x;
        int r = i >> 7, c = i & 127;
        float v = W2[i];
        __nv_bfloat16 h = __float2bfloat16(v);
        g_W2Th[(size_t)c * D_HID + r] = h;
        g_W2Tl[(size_t)c * D_HID + r] = __float2bfloat16(v - __bfloat162float(h));
        return;
    }
    b -= 128;
    {                            // Y split: 3.2M float4 chunks
        int j = b * 256 + threadIdx.x;
        float4 f = __ldg(((const float4*)Y) + j);
        uint2 hi, lo;
        split_f4(f, hi, lo);
        ((uint2*)g_Yh)[j] = hi;
        ((uint2*)g_Yl)[j] = lo;
    }
}

// ---------------- parallel scan (2 phases) --------------------------------------
__global__ void k_scan1() {
    __shared__ int sh[256];
    int t = threadIdx.x;
    int idx = blockIdx.x * 256 + t;
    int v = (idx < N_NODES + 1) ? g_rowptr[idx] : 0;
    sh[t] = v;
    __syncthreads();
#pragma unroll
    for (int off = 1; off < 256; off <<= 1) {
        int u = (t >= off) ? sh[t - off] : 0;
        __syncthreads();
        sh[t] += u;
        __syncthreads();
    }
    if (idx < N_NODES + 1) g_rowptr[idx] = sh[t];
    if (t == 255) g_bsum[blockIdx.x] = sh[255];
}

__global__ void k_scan3() {
    __shared__ int sh[256];
    int t = threadIdx.x;
    sh[t] = (t < (int)blockIdx.x) ? g_bsum[t] : 0;
    __syncthreads();
#pragma unroll
    for (int off = 128; off > 0; off >>= 1) {
        if (t < off) sh[t] += sh[t + off];
        __syncthreads();
    }
    int offset = sh[0];
    int idx = blockIdx.x * 256 + t;
    if (idx < N_NODES + 1) {
        int v = g_rowptr[idx] + offset;
        g_rowptr[idx] = v;
        if (idx < N_NODES) g_cursor[idx] = v;
    }
}

// ---------------- HMMA GEMM core: swizzled smem, cp.async 3-stage ---------------
__device__ __forceinline__ void mma_bf16(float* c, const uint32_t* a, const uint32_t* b) {
    asm("mma.sync.aligned.m16n8k16.row.col.f32.bf16.bf16.f32 "
        "{%0,%1,%2,%3}, {%4,%5,%6,%7}, {%8,%9}, {%0,%1,%2,%3};"
        : "+f"(c[0]), "+f"(c[1]), "+f"(c[2]), "+f"(c[3])
        : "r"(a[0]), "r"(a[1]), "r"(a[2]), "r"(a[3]), "r"(b[0]), "r"(b[1]));
}

#define LDSM4(r0, r1, r2, r3, addr)                                            \
    asm volatile("ldmatrix.sync.aligned.m8n8.x4.shared.b16 {%0,%1,%2,%3}, [%4];" \
                 : "=r"(r0), "=r"(r1), "=r"(r2), "=r"(r3) : "r"(addr))
#define CPA16(dst, src, n)                                                     \
    asm volatile("cp.async.cg.shared.global [%0], [%1], 16, %2;"               \
                 :: "r"(dst), "l"(src), "r"(n))
#define CP_COMMIT() asm volatile("cp.async.commit_group;" ::: "memory")
#define CP_WAIT2()  asm volatile("cp.async.wait_group 2;" ::: "memory")
#define CP_WAIT1()  asm volatile("cp.async.wait_group 1;" ::: "memory")
#define CP_WAIT0()  asm volatile("cp.async.wait_group 0;" ::: "memory")

// stage layout (bytes): Ah@0, Al@8192, Bh@16384, Bl@24576; stage=32768.
// 64B rows (32 bf16); chunk swizzle: phys16B = c ^ ((r>>1)&3)
#define STG  32768
#define T_AL 8192
#define T_BH 16384
#define T_BL 24576
#define NSTG 3

__device__ __forceinline__ void gemm_load_stage(
    uint32_t sb, const __nv_bfloat16* __restrict__ Ah,
    const __nv_bfloat16* __restrict__ Al, const __nv_bfloat16* __restrict__ Bh,
    const __nv_bfloat16* __restrict__ Bl, int rowBase, int colBase, int M,
    int k0, int tid)
{
#pragma unroll
    for (int it = 0; it < 2; it++) {
        int ch = tid + it * 256;
        int r = ch >> 2, c = ch & 3;
        uint32_t so = (uint32_t)(r * 64 + ((c ^ ((r >> 1) & 3)) * 16));
        int gr = rowBase + r;
        int ok = (gr < M) ? 16 : 0;
        int grc = (gr < M) ? gr : (M - 1);
        size_t aoff = (size_t)grc * 256 + k0 + c * 8;
        CPA16(sb + so,        Ah + aoff, ok);
        CPA16(sb + T_AL + so, Al + aoff, ok);
        size_t boff = (size_t)(colBase + r) * 256 + k0 + c * 8;
        CPA16(sb + T_BH + so, Bh + boff, 16);
        CPA16(sb + T_BL + so, Bl + boff, 16);
    }
}

__device__ __forceinline__ void gemm_core(
    const __nv_bfloat16* __restrict__ Ah, const __nv_bfloat16* __restrict__ Al,
    const __nv_bfloat16* __restrict__ Bh, const __nv_bfloat16* __restrict__ Bl,
    float* __restrict__ C, int M, int N, int bx, int by)
{
    extern __shared__ __align__(128) char dsm[];
    uint32_t sb = (uint32_t)__cvta_generic_to_shared(dsm);

    int tid = threadIdx.x;
    int lane = tid & 31, wid = tid >> 5;
    int rowBase = by * 128, colBase = bx * 128;
    int wm = (wid >> 2) * 64;
    int wn = (wid & 3) * 32;

    float acc[4][4][4];
#pragma unroll
    for (int mi = 0; mi < 4; mi++)
#pragma unroll
        for (int ni = 0; ni < 4; ni++)
#pragma unroll
            for (int q = 0; q < 4; q++) acc[mi][ni][q] = 0.f;

    // per-lane fragment row bases + swizzle keys
    uint32_t aRow[4], aS[4], bRow[2], bS[2];
    uint32_t kaBase = (lane & 16) ? 16u : 0u;
    uint32_t kbBase = (lane & 8) ? 16u : 0u;
    {
        int ra = (lane & 7) + ((lane & 8) ? 8 : 0);
#pragma unroll
        for (int mi = 0; mi < 4; mi++) {
            int r = wm + mi * 16 + ra;
            aRow[mi] = (uint32_t)(r * 64);
            aS[mi]   = (uint32_t)(((r >> 1) & 3) * 16);
        }
        int rb = (lane & 7) + ((lane & 16) ? 8 : 0);
#pragma unroll
        for (int p = 0; p < 2; p++) {
            int r = wn + p * 16 + rb;
            bRow[p] = (uint32_t)(r * 64);
            bS[p]   = (uint32_t)(((r >> 1) & 3) * 16);
        }
    }

    gemm_load_stage(sb, Ah, Al, Bh, Bl, rowBase, colBase, M, 0, tid);
    CP_COMMIT();
    gemm_load_stage(sb + STG, Ah, Al, Bh, Bl, rowBase, colBase, M, 32, tid);
    CP_COMMIT();

    const int KT = 8;
    for (int kt = 0; kt < KT; kt++) {
        uint32_t cur = sb + (uint32_t)(kt % NSTG) * STG;
        if (kt < KT - 2) {
            gemm_load_stage(sb + (uint32_t)((kt + 2) % NSTG) * STG,
                            Ah, Al, Bh, Bl, rowBase, colBase, M,
                            (kt + 2) * 32, tid);
            CP_COMMIT();
            CP_WAIT2();
        } else if (kt == KT - 2) {
            CP_WAIT1();
        } else {
            CP_WAIT0();
        }
        __syncthreads();

#pragma unroll
        for (int ks = 0; ks < 2; ks++) {
            uint32_t kA = (uint32_t)(ks * 32) + kaBase;
            uint32_t kB = (uint32_t)(ks * 32) + kbBase;
            uint32_t bhr[8], blr[8], af[4][4];
            // load ALL B fragments and ALL Ah fragments first
            LDSM4(bhr[0], bhr[1], bhr[2], bhr[3],
                  cur + T_BH + bRow[0] + (kB ^ bS[0]));
            LDSM4(bhr[4], bhr[5], bhr[6], bhr[7],
                  cur + T_BH + bRow[1] + (kB ^ bS[1]));
            LDSM4(blr[0], blr[1], blr[2], blr[3],
                  cur + T_BL + bRow[0] + (kB ^ bS[0]));
            LDSM4(blr[4], blr[5], blr[6], blr[7],
                  cur + T_BL + bRow[1] + (kB ^ bS[1]));
#pragma unroll
            for (int mi = 0; mi < 4; mi++)
                LDSM4(af[mi][0], af[mi][1], af[mi][2], af[mi][3],
                      cur + aRow[mi] + (kA ^ aS[mi]));
            // term-major: same-acc writes are 16 HMMAs apart (no dep stalls)
#pragma unroll
            for (int mi = 0; mi < 4; mi++)
#pragma unroll
                for (int ni = 0; ni < 4; ni++)
                    mma_bf16(acc[mi][ni], af[mi], &bhr[ni * 2]);
#pragma unroll
            for (int mi = 0; mi < 4; mi++)
#pragma unroll
                for (int ni = 0; ni < 4; ni++)
                    mma_bf16(acc[mi][ni], af[mi], &blr[ni * 2]);
            // reload Al into the same fragment registers
#pragma unroll
            for (int mi = 0; mi < 4; mi++)
                LDSM4(af[mi][0], af[mi][1], af[mi][2], af[mi][3],
                      cur + T_AL + aRow[mi] + (kA ^ aS[mi]));
#pragma unroll
            for (int mi = 0; mi < 4; mi++)
#pragma unroll
                for (int ni = 0; ni < 4; ni++)
                    mma_bf16(acc[mi][ni], af[mi], &bhr[ni * 2]);
        }
        if (kt + 1 < KT) __syncthreads();
    }

#pragma unroll
    for (int mi = 0; mi < 4; mi++) {
        int rr = rowBase + wm + mi * 16 + (lane >> 2);
#pragma unroll
        for (int ni = 0; ni < 4; ni++) {
            int cc = colBase + wn + ni * 8 + (lane & 3) * 2;
            if (rr < M)
                *(float2*)&C[(size_t)rr * N + cc] =
                    make_float2(acc[mi][ni][0], acc[mi][ni][1]);
            if (rr + 8 < M)
                *(float2*)&C[(size_t)(rr + 8) * N + cc] =
                    make_float2(acc[mi][ni][2], acc[mi][ni][3]);
        }
    }
}

// ---------------- GEMM1 with scatter slice appended ------------------------------
__global__ __launch_bounds__(256, 2)
void k_gemm1_scatter(float* __restrict__ H1,
                     const int* __restrict__ erow, const int* __restrict__ ecol,
                     const float* __restrict__ eval)
{
    gemm_core(g_Yh, g_Yl, g_W1Th, g_W1Tl, H1, N_NODES, D_HID,
              blockIdx.x & 1, blockIdx.x >> 1);
    int base = blockIdx.x * EPB + threadIdx.x;
#pragma unroll
    for (int q = 0; q < EPB / 256; q++) {
        int i = base + q * 256;
        if (i < N_EDGES) {
            int r = erow[i];
            int p = atomicAdd(&g_cursor[r], 1);
            g_ecv[p] = make_int2(ecol[i], __float_as_int(eval[i]));
        }
    }
}

__global__ __launch_bounds__(256, 2)
void k_gemm2(float* __restrict__ H3)
{
    gemm_core(g_H2h, g_H2l, g_W2Th, g_W2Tl, H3, N_NODES, D_OUT, 0, blockIdx.x);
}

// ---------------- SpMM1: H2{h,l} = split(relu(spmm(H1))), 4-wide unrolled --------
__global__ void k_spmm1(const float* __restrict__ X) {
    int r = blockIdx.x * 4 + threadIdx.y;
    if (r >= N_NODES) return;
    int f4 = threadIdx.x * 4;               // 64 lanes x 4 feats = 256
    int e   = g_rowptr[r];
    int end = g_rowptr[r + 1];
    float4 acc = make_float4(0.f, 0.f, 0.f, 0.f);
    for (; e + 4 <= end; e += 4) {
        int2 cv0 = __ldg(&g_ecv[e]);
        int2 cv1 = __ldg(&g_ecv[e + 1]);
        int2 cv2 = __ldg(&g_ecv[e + 2]);
        int2 cv3 = __ldg(&g_ecv[e + 3]);
        float4 x0 = __ldg((const float4*)&X[(size_t)cv0.x * D_HID + f4]);
        float4 x1 = __ldg((const float4*)&X[(size_t)cv1.x * D_HID + f4]);
        float4 x2 = __ldg((const float4*)&X[(size_t)cv2.x * D_HID + f4]);
        float4 x3 = __ldg((const float4*)&X[(size_t)cv3.x * D_HID + f4]);
        float v0 = __int_as_float(cv0.y), v1 = __int_as_float(cv1.y);
        float v2 = __int_as_float(cv2.y), v3 = __int_as_float(cv3.y);
        acc.x += v0 * x0.x; acc.y += v0 * x0.y; acc.z += v0 * x0.z; acc.w += v0 * x0.w;
        acc.x += v1 * x1.x; acc.y += v1 * x1.y; acc.z += v1 * x1.z; acc.w += v1 * x1.w;
        acc.x += v2 * x2.x; acc.y += v2 * x2.y; acc.z += v2 * x2.z; acc.w += v2 * x2.w;
        acc.x += v3 * x3.x; acc.y += v3 * x3.y; acc.z += v3 * x3.z; acc.w += v3 * x3.w;
    }
    for (; e < end; e++) {
        int2 cv = __ldg(&g_ecv[e]);
        float v = __int_as_float(cv.y);
        float4 x = __ldg((const float4*)&X[(size_t)cv.x * D_HID + f4]);
        acc.x += v * x.x; acc.y += v * x.y; acc.z += v * x.z; acc.w += v * x.w;
    }
    acc.x = fmaxf(acc.x, 0.f); acc.y = fmaxf(acc.y, 0.f);
    acc.z = fmaxf(acc.z, 0.f); acc.w = fmaxf(acc.w, 0.f);
    uint2 hi, lo;
    split_f4(acc, hi, lo);
    *(uint2*)&g_H2h[(size_t)r * D_HID + f4] = hi;
    *(uint2*)&g_H2l[(size_t)r * D_HID + f4] = lo;
}

// ---------------- SpMM2: out = spmm(H3), 4-wide unrolled --------------------------
__global__ void k_spmm2(const float* __restrict__ X, float* __restrict__ out) {
    int r = blockIdx.x * 8 + threadIdx.y;
    if (r >= N_NODES) return;
    int f4 = threadIdx.x * 4;               // 32 lanes x 4 feats = 128
    int e   = g_rowptr[r];
    int end = g_rowptr[r + 1];
    float4 acc = make_float4(0.f, 0.f, 0.f, 0.f);
    for (; e + 4 <= end; e += 4) {
        int2 cv0 = __ldg(&g_ecv[e]);
        int2 cv1 = __ldg(&g_ecv[e + 1]);
        int2 cv2 = __ldg(&g_ecv[e + 2]);
        int2 cv3 = __ldg(&g_ecv[e + 3]);
        float4 x0 = __ldg((const float4*)&X[(size_t)cv0.x * D_OUT + f4]);
        float4 x1 = __ldg((const float4*)&X[(size_t)cv1.x * D_OUT + f4]);
        float4 x2 = __ldg((const float4*)&X[(size_t)cv2.x * D_OUT + f4]);
        float4 x3 = __ldg((const float4*)&X[(size_t)cv3.x * D_OUT + f4]);
        float v0 = __int_as_float(cv0.y), v1 = __int_as_float(cv1.y);
        float v2 = __int_as_float(cv2.y), v3 = __int_as_float(cv3.y);
        acc.x += v0 * x0.x; acc.y += v0 * x0.y; acc.z += v0 * x0.z; acc.w += v0 * x0.w;
        acc.x += v1 * x1.x; acc.y += v1 * x1.y; acc.z += v1 * x1.z; acc.w += v1 * x1.w;
        acc.x += v2 * x2.x; acc.y += v2 * x2.y; acc.z += v2 * x2.z; acc.w += v2 * x2.w;
        acc.x += v3 * x3.x; acc.y += v3 * x3.y; acc.z += v3 * x3.z; acc.w += v3 * x3.w;
    }
    for (; e < end; e++) {
        int2 cv = __ldg(&g_ecv[e]);
        float v = __int_as_float(cv.y);
        float4 x = __ldg((const float4*)&X[(size_t)cv.x * D_OUT + f4]);
        acc.x += v * x.x; acc.y += v * x.y; acc.z += v * x.z; acc.w += v * x.w;
    }
    *(float4*)&out[(size_t)r * D_OUT + f4] = acc;
}

// ---------------- launch -----------------------------------------------------------
extern "C" void kernel_launch(void* const* d_in, const int* in_sizes, int n_in,
                              void* d_out, int out_size) {
    const float* Y        = (const float*)d_in[0];
    const int*   edge_row = (const int*)d_in[1];
    const int*   edge_col = (const int*)d_in[2];
    const float* edge_val = (const float*)d_in[3];
    const float* W1       = (const float*)d_in[4];
    const float* W2       = (const float*)d_in[5];
    float*       out      = (float*)d_out;

    float *pH1, *pH3;
    int *pRowptr;
    cudaGetSymbolAddress((void**)&pH1, g_H1);
    cudaGetSymbolAddress((void**)&pH3, g_H3);
    cudaGetSymbolAddress((void**)&pRowptr, g_rowptr);

    const int DSM = NSTG * STG;   // 98304 B
    cudaFuncSetAttribute(k_gemm1_scatter,
                         cudaFuncAttributeMaxDynamicSharedMemorySize, DSM);
    cudaFuncSetAttribute(k_gemm2,
                         cudaFuncAttributeMaxDynamicSharedMemorySize, DSM);

    cudaMemsetAsync(pRowptr, 0, (N_NODES + 1) * sizeof(int));
    k_init_all<<<HISTB + 256 + 128 + YSPB, 256>>>(edge_row, W1, W2, Y);
    k_scan1<<<196, 256>>>();
    k_scan3<<<196, 256>>>();
    k_gemm1_scatter<<<G1B, 256, DSM>>>(pH1, edge_row, edge_col, edge_val);
    {
        dim3 blk(64, 4);
        k_spmm1<<<(N_NODES + 3) / 4, blk>>>(pH1);
    }
    k_gemm2<<<GRID_M, 256, DSM>>>(pH3);
    {
        dim3 blk(32, 8);
        k_spmm2<<<(N_NODES + 7) / 8, blk>>>(pH3, out);
    }
}

// round 11
// speedup vs baseline: 1.0595x; 1.0595x over previous
#include <cuda_runtime.h>
#include <cuda_bf16.h>
#include <cuda_fp16.h>
#include <cstdint>

#define N_NODES 50000
#define N_EDGES 800000
#define D_IN    256
#define D_HID   256
#define D_OUT   128
#define GRID_M  391            // ceil(50000/128)
#define HISTB   3125           // ceil(800000/256)
#define YSPB    12500          // 50000*256/4 float4 / 256 threads
#define G1B     (2 * GRID_M)   // 782 GEMM1 blocks
#define EPB     1024           // edges scattered per GEMM1 block

// ---------------- scratch ------------------------------------------------------
__device__ __half g_H1[(size_t)N_NODES * D_HID];    // fp16: halves SpMM1 gather
__device__ __nv_bfloat16 g_H2h[(size_t)N_NODES * D_HID];
__device__ __nv_bfloat16 g_H2l[(size_t)N_NODES * D_HID];
__device__ __half g_H3[(size_t)N_NODES * D_OUT];    // fp16: halves SpMM2 gather
__device__ __nv_bfloat16 g_Yh[(size_t)N_NODES * D_IN];
__device__ __nv_bfloat16 g_Yl[(size_t)N_NODES * D_IN];
__device__ __nv_bfloat16 g_W1Th[D_HID * D_IN];
__device__ __nv_bfloat16 g_W1Tl[D_HID * D_IN];
__device__ __nv_bfloat16 g_W2Th[D_OUT * D_HID];
__device__ __nv_bfloat16 g_W2Tl[D_OUT * D_HID];
__device__ int   g_rowptr[N_NODES + 1];
__device__ int   g_cursor[N_NODES];
__device__ int   g_bsum[256];
__device__ int2  g_ecv[N_EDGES];

// ---------------- helpers ------------------------------------------------------
__device__ __forceinline__ void split_f4(float4 f, uint2& hi, uint2& lo) {
    __nv_bfloat162 h01 = __floats2bfloat162_rn(f.x, f.y);
    __nv_bfloat162 h23 = __floats2bfloat162_rn(f.z, f.w);
    float2 g01 = __bfloat1622float2(h01);
    float2 g23 = __bfloat1622float2(h23);
    __nv_bfloat162 l01 = __floats2bfloat162_rn(f.x - g01.x, f.y - g01.y);
    __nv_bfloat162 l23 = __floats2bfloat162_rn(f.z - g23.x, f.w - g23.y);
    hi.x = *(uint32_t*)&h01; hi.y = *(uint32_t*)&h23;
    lo.x = *(uint32_t*)&l01; lo.y = *(uint32_t*)&l23;
}

// ---------------- K1: hist + W splits + Y split --------------------------------
__global__ void k_init_all(const int* __restrict__ erow,
                           const float* __restrict__ W1,
                           const float* __restrict__ W2,
                           const float* __restrict__ Y) {
    int b = blockIdx.x;
    if (b < HISTB) {
        int i = b * 256 + threadIdx.x;
        if (i < N_EDGES) atomicAdd(&g_rowptr[erow[i] + 1], 1);
        return;
    }
    b -= HISTB;
    if (b < 256) {               // W1 [256][256] -> T split
        int i = b * 256 + threadIdx.x;
        int r = i >> 8, c = i & 255;
        float v = W1[i];
        __nv_bfloat16 h = __float2bfloat16(v);
        g_W1Th[(size_t)c * D_IN + r] = h;
        g_W1Tl[(size_t)c * D_IN + r] = __float2bfloat16(v - __bfloat162float(h));
        return;
    }
    b -= 256;
    if (b < 128) {               // W2 [256][128] -> T split
        int i = b * 256 + threadIdx.x;
        int r = i >> 7, c = i & 127;
        float v = W2[i];
        __nv_bfloat16 h = __float2bfloat16(v);
        g_W2Th[(size_t)c * D_HID + r] = h;
        g_W2Tl[(size_t)c * D_HID + r] = __float2bfloat16(v - __bfloat162float(h));
        return;
    }
    b -= 128;
    {                            // Y split: 3.2M float4 chunks
        int j = b * 256 + threadIdx.x;
        float4 f = __ldg(((const float4*)Y) + j);
        uint2 hi, lo;
        split_f4(f, hi, lo);
        ((uint2*)g_Yh)[j] = hi;
        ((uint2*)g_Yl)[j] = lo;
    }
}

// ---------------- parallel scan (2 phases) --------------------------------------
__global__ void k_scan1() {
    __shared__ int sh[256];
    int t = threadIdx.x;
    int idx = blockIdx.x * 256 + t;
    int v = (idx < N_NODES + 1) ? g_rowptr[idx] : 0;
    sh[t] = v;
    __syncthreads();
#pragma unroll
    for (int off = 1; off < 256; off <<= 1) {
        int u = (t >= off) ? sh[t - off] : 0;
        __syncthreads();
        sh[t] += u;
        __syncthreads();
    }
    if (idx < N_NODES + 1) g_rowptr[idx] = sh[t];
    if (t == 255) g_bsum[blockIdx.x] = sh[255];
}

__global__ void k_scan3() {
    __shared__ int sh[256];
    int t = threadIdx.x;
    sh[t] = (t < (int)blockIdx.x) ? g_bsum[t] : 0;
    __syncthreads();
#pragma unroll
    for (int off = 128; off > 0; off >>= 1) {
        if (t < off) sh[t] += sh[t + off];
        __syncthreads();
    }
    int offset = sh[0];
    int idx = blockIdx.x * 256 + t;
    if (idx < N_NODES + 1) {
        int v = g_rowptr[idx] + offset;
        g_rowptr[idx] = v;
        if (idx < N_NODES) g_cursor[idx] = v;
    }
}

// ---------------- HMMA GEMM core: swizzled smem, cp.async 3-stage ---------------
__device__ __forceinline__ void mma_bf16(float* c, const uint32_t* a, const uint32_t* b) {
    asm("mma.sync.aligned.m16n8k16.row.col.f32.bf16.bf16.f32 "
        "{%0,%1,%2,%3}, {%4,%5,%6,%7}, {%8,%9}, {%0,%1,%2,%3};"
        : "+f"(c[0]), "+f"(c[1]), "+f"(c[2]), "+f"(c[3])
        : "r"(a[0]), "r"(a[1]), "r"(a[2]), "r"(a[3]), "r"(b[0]), "r"(b[1]));
}

#define LDSM4(r0, r1, r2, r3, addr)                                            \
    asm volatile("ldmatrix.sync.aligned.m8n8.x4.shared.b16 {%0,%1,%2,%3}, [%4];" \
                 : "=r"(r0), "=r"(r1), "=r"(r2), "=r"(r3) : "r"(addr))
#define CPA16(dst, src, n)                                                     \
    asm volatile("cp.async.cg.shared.global [%0], [%1], 16, %2;"               \
                 :: "r"(dst), "l"(src), "r"(n))
#define CP_COMMIT() asm volatile("cp.async.commit_group;" ::: "memory")
#define CP_WAIT2()  asm volatile("cp.async.wait_group 2;" ::: "memory")
#define CP_WAIT1()  asm volatile("cp.async.wait_group 1;" ::: "memory")
#define CP_WAIT0()  asm volatile("cp.async.wait_group 0;" ::: "memory")

// stage layout (bytes): Ah@0, Al@8192, Bh@16384, Bl@24576; stage=32768.
// 64B rows (32 bf16); chunk swizzle: phys16B = c ^ ((r>>1)&3)
#define STG  32768
#define T_AL 8192
#define T_BH 16384
#define T_BL 24576
#define NSTG 3

__device__ __forceinline__ void gemm_load_stage(
    uint32_t sb, const __nv_bfloat16* __restrict__ Ah,
    const __nv_bfloat16* __restrict__ Al, const __nv_bfloat16* __restrict__ Bh,
    const __nv_bfloat16* __restrict__ Bl, int rowBase, int colBase, int M,
    int k0, int tid)
{
#pragma unroll
    for (int it = 0; it < 2; it++) {
        int ch = tid + it * 256;
        int r = ch >> 2, c = ch & 3;
        uint32_t so = (uint32_t)(r * 64 + ((c ^ ((r >> 1) & 3)) * 16));
        int gr = rowBase + r;
        int ok = (gr < M) ? 16 : 0;
        int grc = (gr < M) ? gr : (M - 1);
        size_t aoff = (size_t)grc * 256 + k0 + c * 8;
        CPA16(sb + so,        Ah + aoff, ok);
        CPA16(sb + T_AL + so, Al + aoff, ok);
        size_t boff = (size_t)(colBase + r) * 256 + k0 + c * 8;
        CPA16(sb + T_BH + so, Bh + boff, 16);
        CPA16(sb + T_BL + so, Bl + boff, 16);
    }
}

// C is written in fp16 (half2 stores)
__device__ __forceinline__ void gemm_core(
    const __nv_bfloat16* __restrict__ Ah, const __nv_bfloat16* __restrict__ Al,
    const __nv_bfloat16* __restrict__ Bh, const __nv_bfloat16* __restrict__ Bl,
    __half* __restrict__ C, int M, int N, int bx, int by)
{
    extern __shared__ __align__(128) char dsm[];
    uint32_t sb = (uint32_t)__cvta_generic_to_shared(dsm);

    int tid = threadIdx.x;
    int lane = tid & 31, wid = tid >> 5;
    int rowBase = by * 128, colBase = bx * 128;
    int wm = (wid >> 2) * 64;
    int wn = (wid & 3) * 32;

    float acc[4][4][4];
#pragma unroll
    for (int mi = 0; mi < 4; mi++)
#pragma unroll
        for (int ni = 0; ni < 4; ni++)
#pragma unroll
            for (int q = 0; q < 4; q++) acc[mi][ni][q] = 0.f;

    uint32_t aRow[4], aS[4], bRow[2], bS[2];
    uint32_t kaBase = (lane & 16) ? 16u : 0u;
    uint32_t kbBase = (lane & 8) ? 16u : 0u;
    {
        int ra = (lane & 7) + ((lane & 8) ? 8 : 0);
#pragma unroll
        for (int mi = 0; mi < 4; mi++) {
            int r = wm + mi * 16 + ra;
            aRow[mi] = (uint32_t)(r * 64);
            aS[mi]   = (uint32_t)(((r >> 1) & 3) * 16);
        }
        int rb = (lane & 7) + ((lane & 16) ? 8 : 0);
#pragma unroll
        for (int p = 0; p < 2; p++) {
            int r = wn + p * 16 + rb;
            bRow[p] = (uint32_t)(r * 64);
            bS[p]   = (uint32_t)(((r >> 1) & 3) * 16);
        }
    }

    gemm_load_stage(sb, Ah, Al, Bh, Bl, rowBase, colBase, M, 0, tid);
    CP_COMMIT();
    gemm_load_stage(sb + STG, Ah, Al, Bh, Bl, rowBase, colBase, M, 32, tid);
    CP_COMMIT();

    const int KT = 8;
    for (int kt = 0; kt < KT; kt++) {
        uint32_t cur = sb + (uint32_t)(kt % NSTG) * STG;
        if (kt < KT - 2) {
            gemm_load_stage(sb + (uint32_t)((kt + 2) % NSTG) * STG,
                            Ah, Al, Bh, Bl, rowBase, colBase, M,
                            (kt + 2) * 32, tid);
            CP_COMMIT();
            CP_WAIT2();
        } else if (kt == KT - 2) {
            CP_WAIT1();
        } else {
            CP_WAIT0();
        }
        __syncthreads();

#pragma unroll
        for (int ks = 0; ks < 2; ks++) {
            uint32_t kA = (uint32_t)(ks * 32) + kaBase;
            uint32_t kB = (uint32_t)(ks * 32) + kbBase;
            uint32_t bhr[8], blr[8], af[4][4];
            LDSM4(bhr[0], bhr[1], bhr[2], bhr[3],
                  cur + T_BH + bRow[0] + (kB ^ bS[0]));
            LDSM4(bhr[4], bhr[5], bhr[6], bhr[7],
                  cur + T_BH + bRow[1] + (kB ^ bS[1]));
            LDSM4(blr[0], blr[1], blr[2], blr[3],
                  cur + T_BL + bRow[0] + (kB ^ bS[0]));
            LDSM4(blr[4], blr[5], blr[6], blr[7],
                  cur + T_BL + bRow[1] + (kB ^ bS[1]));
#pragma unroll
            for (int mi = 0; mi < 4; mi++)
                LDSM4(af[mi][0], af[mi][1], af[mi][2], af[mi][3],
                      cur + aRow[mi] + (kA ^ aS[mi]));
#pragma unroll
            for (int mi = 0; mi < 4; mi++)
#pragma unroll
                for (int ni = 0; ni < 4; ni++)
                    mma_bf16(acc[mi][ni], af[mi], &bhr[ni * 2]);
#pragma unroll
            for (int mi = 0; mi < 4; mi++)
#pragma unroll
                for (int ni = 0; ni < 4; ni++)
                    mma_bf16(acc[mi][ni], af[mi], &blr[ni * 2]);
#pragma unroll
            for (int mi = 0; mi < 4; mi++)
                LDSM4(af[mi][0], af[mi][1], af[mi][2], af[mi][3],
                      cur + T_AL + aRow[mi] + (kA ^ aS[mi]));
#pragma unroll
            for (int mi = 0; mi < 4; mi++)
#pragma unroll
                for (int ni = 0; ni < 4; ni++)
                    mma_bf16(acc[mi][ni], af[mi], &bhr[ni * 2]);
        }
        if (kt + 1 < KT) __syncthreads();
    }

#pragma unroll
    for (int mi = 0; mi < 4; mi++) {
        int rr = rowBase + wm + mi * 16 + (lane >> 2);
#pragma unroll
        for (int ni = 0; ni < 4; ni++) {
            int cc = colBase + wn + ni * 8 + (lane & 3) * 2;
            if (rr < M)
                *(__half2*)&C[(size_t)rr * N + cc] =
                    __floats2half2_rn(acc[mi][ni][0], acc[mi][ni][1]);
            if (rr + 8 < M)
                *(__half2*)&C[(size_t)(rr + 8) * N + cc] =
                    __floats2half2_rn(acc[mi][ni][2], acc[mi][ni][3]);
        }
    }
}

// ---------------- GEMM1 with scatter slice appended ------------------------------
__global__ __launch_bounds__(256, 2)
void k_gemm1_scatter(const int* __restrict__ erow, const int* __restrict__ ecol,
                     const float* __restrict__ eval)
{
    gemm_core(g_Yh, g_Yl, g_W1Th, g_W1Tl, g_H1, N_NODES, D_HID,
              blockIdx.x & 1, blockIdx.x >> 1);
    int base = blockIdx.x * EPB + threadIdx.x;
#pragma unroll
    for (int q = 0; q < EPB / 256; q++) {
        int i = base + q * 256;
        if (i < N_EDGES) {
            int r = erow[i];
            int p = atomicAdd(&g_cursor[r], 1);
            g_ecv[p] = make_int2(ecol[i], __float_as_int(eval[i]));
        }
    }
}

__global__ __launch_bounds__(256, 2)
void k_gemm2()
{
    gemm_core(g_H2h, g_H2l, g_W2Th, g_W2Tl, g_H3, N_NODES, D_OUT, 0, blockIdx.x);
}

// fp16 gather helper: 4 halves -> float4 accumulate
__device__ __forceinline__ void fma_h4(float4& acc, float v, uint2 raw) {
    float2 a01 = __half22float2(*(__half2*)&raw.x);
    float2 a23 = __half22float2(*(__half2*)&raw.y);
    acc.x += v * a01.x; acc.y += v * a01.y;
    acc.z += v * a23.x; acc.w += v * a23.y;
}

// ---------------- SpMM1: H2{h,l} = split(relu(spmm(H1fp16))), 4-wide -------------
__global__ void k_spmm1() {
    int r = blockIdx.x * 4 + threadIdx.y;
    if (r >= N_NODES) return;
    int f4 = threadIdx.x * 4;               // 64 lanes x 4 feats = 256
    int e   = g_rowptr[r];
    int end = g_rowptr[r + 1];
    float4 acc = make_float4(0.f, 0.f, 0.f, 0.f);
    for (; e + 4 <= end; e += 4) {
        int2 cv0 = __ldg(&g_ecv[e]);
        int2 cv1 = __ldg(&g_ecv[e + 1]);
        int2 cv2 = __ldg(&g_ecv[e + 2]);
        int2 cv3 = __ldg(&g_ecv[e + 3]);
        uint2 x0 = __ldg((const uint2*)&g_H1[(size_t)cv0.x * D_HID + f4]);
        uint2 x1 = __ldg((const uint2*)&g_H1[(size_t)cv1.x * D_HID + f4]);
        uint2 x2 = __ldg((const uint2*)&g_H1[(size_t)cv2.x * D_HID + f4]);
        uint2 x3 = __ldg((const uint2*)&g_H1[(size_t)cv3.x * D_HID + f4]);
        fma_h4(acc, __int_as_float(cv0.y), x0);
        fma_h4(acc, __int_as_float(cv1.y), x1);
        fma_h4(acc, __int_as_float(cv2.y), x2);
        fma_h4(acc, __int_as_float(cv3.y), x3);
    }
    for (; e < end; e++) {
        int2 cv = __ldg(&g_ecv[e]);
        uint2 x = __ldg((const uint2*)&g_H1[(size_t)cv.x * D_HID + f4]);
        fma_h4(acc, __int_as_float(cv.y), x);
    }
    acc.x = fmaxf(acc.x, 0.f); acc.y = fmaxf(acc.y, 0.f);
    acc.z = fmaxf(acc.z, 0.f); acc.w = fmaxf(acc.w, 0.f);
    uint2 hi, lo;
    split_f4(acc, hi, lo);
    *(uint2*)&g_H2h[(size_t)r * D_HID + f4] = hi;
    *(uint2*)&g_H2l[(size_t)r * D_HID + f4] = lo;
}

// ---------------- SpMM2: out = spmm(H3fp16), 4-wide -------------------------------
__global__ void k_spmm2(float* __restrict__ out) {
    int r = blockIdx.x * 8 + threadIdx.y;
    if (r >= N_NODES) return;
    int f4 = threadIdx.x * 4;               // 32 lanes x 4 feats = 128
    int e   = g_rowptr[r];
    int end = g_rowptr[r + 1];
    float4 acc = make_float4(0.f, 0.f, 0.f, 0.f);
    for (; e + 4 <= end; e += 4) {
        int2 cv0 = __ldg(&g_ecv[e]);
        int2 cv1 = __ldg(&g_ecv[e + 1]);
        int2 cv2 = __ldg(&g_ecv[e + 2]);
        int2 cv3 = __ldg(&g_ecv[e + 3]);
        uint2 x0 = __ldg((const uint2*)&g_H3[(size_t)cv0.x * D_OUT + f4]);
        uint2 x1 = __ldg((const uint2*)&g_H3[(size_t)cv1.x * D_OUT + f4]);
        uint2 x2 = __ldg((const uint2*)&g_H3[(size_t)cv2.x * D_OUT + f4]);
        uint2 x3 = __ldg((const uint2*)&g_H3[(size_t)cv3.x * D_OUT + f4]);
        fma_h4(acc, __int_as_float(cv0.y), x0);
        fma_h4(acc, __int_as_float(cv1.y), x1);
        fma_h4(acc, __int_as_float(cv2.y), x2);
        fma_h4(acc, __int_as_float(cv3.y), x3);
    }
    for (; e < end; e++) {
        int2 cv = __ldg(&g_ecv[e]);
        uint2 x = __ldg((const uint2*)&g_H3[(size_t)cv.x * D_OUT + f4]);
        fma_h4(acc, __int_as_float(cv.y), x);
    }
    *(float4*)&out[(size_t)r * D_OUT + f4] = acc;
}

// ---------------- launch -----------------------------------------------------------
extern "C" void kernel_launch(void* const* d_in, const int* in_sizes, int n_in,
                              void* d_out, int out_size) {
    const float* Y        = (const float*)d_in[0];
    const int*   edge_row = (const int*)d_in[1];
    const int*   edge_col = (const int*)d_in[2];
    const float* edge_val = (const float*)d_in[3];
    const float* W1       = (const float*)d_in[4];
    const float* W2       = (const float*)d_in[5];
    float*       out      = (float*)d_out;

    int *pRowptr;
    cudaGetSymbolAddress((void**)&pRowptr, g_rowptr);

    const int DSM = NSTG * STG;   // 98304 B
    cudaFuncSetAttribute(k_gemm1_scatter,
                         cudaFuncAttributeMaxDynamicSharedMemorySize, DSM);
    cudaFuncSetAttribute(k_gemm2,
                         cudaFuncAttributeMaxDynamicSharedMemorySize, DSM);

    cudaMemsetAsync(pRowptr, 0, (N_NODES + 1) * sizeof(int));
    k_init_all<<<HISTB + 256 + 128 + YSPB, 256>>>(edge_row, W1, W2, Y);
    k_scan1<<<196, 256>>>();
    k_scan3<<<196, 256>>>();
    k_gemm1_scatter<<<G1B, 256, DSM>>>(edge_row, edge_col, edge_val);
    {
        dim3 blk(64, 4);
        k_spmm1<<<(N_NODES + 3) / 4, blk>>>();
    }
    k_gemm2<<<GRID_M, 256, DSM>>>();
    {
        dim3 blk(32, 8);
        k_spmm2<<<(N_NODES + 7) / 8, blk>>>(out);
    }
}

// round 12
// speedup vs baseline: 1.3656x; 1.2889x over previous
#include <cuda_runtime.h>
#include <cuda_fp16.h>
#include <cstdint>

#define N_NODES 50000
#define N_EDGES 800000
#define D_IN    256
#define D_HID   256
#define D_OUT   128
#define GRID_M  391            // ceil(50000/128)
#define HISTB   3125           // ceil(800000/256)
#define YSPB    12500          // 50000*256/4 float4 / 256 threads
#define G1B     (2 * GRID_M)   // 782 GEMM1 blocks
#define EPB     1024           // edges scattered per GEMM1 block

// ---------------- scratch ------------------------------------------------------
__device__ __half g_H1[(size_t)N_NODES * D_HID];
__device__ __half g_H2[(size_t)N_NODES * D_HID];
__device__ __half g_H3[(size_t)N_NODES * D_OUT];
__device__ __half g_Yh[(size_t)N_NODES * D_IN];
__device__ __half g_W1T[D_HID * D_IN];
__device__ __half g_W2T[D_OUT * D_HID];
__device__ int   g_rowptr[N_NODES + 1];
__device__ int   g_cursor[N_NODES];
__device__ int   g_bsum[256];
__device__ int2  g_ecv[N_EDGES];

// ---------------- K1: hist + W transposes (fp16) + Y convert -------------------
__global__ void k_init_all(const int* __restrict__ erow,
                           const float* __restrict__ W1,
                           const float* __restrict__ W2,
                           const float* __restrict__ Y) {
    int b = blockIdx.x;
    if (b < HISTB) {
        int i = b * 256 + threadIdx.x;
        if (i < N_EDGES) atomicAdd(&g_rowptr[erow[i] + 1], 1);
        return;
    }
    b -= HISTB;
    if (b < 256) {               // W1 [256][256] -> T fp16
        int i = b * 256 + threadIdx.x;
        int r = i >> 8, c = i & 255;
        g_W1T[(size_t)c * D_IN + r] = __float2half(W1[i]);
        return;
    }
    b -= 256;
    if (b < 128) {               // W2 [256][128] -> T fp16
        int i = b * 256 + threadIdx.x;
        int r = i >> 7, c = i & 127;
        g_W2T[(size_t)c * D_HID + r] = __float2half(W2[i]);
        return;
    }
    b -= 128;
    {                            // Y convert: 3.2M float4 chunks -> 4x fp16
        int j = b * 256 + threadIdx.x;
        float4 f = __ldg(((const float4*)Y) + j);
        uint2 h;
        __half2 h01 = __floats2half2_rn(f.x, f.y);
        __half2 h23 = __floats2half2_rn(f.z, f.w);
        h.x = *(uint32_t*)&h01; h.y = *(uint32_t*)&h23;
        ((uint2*)g_Yh)[j] = h;
    }
}

// ---------------- parallel scan (2 phases) --------------------------------------
__global__ void k_scan1() {
    __shared__ int sh[256];
    int t = threadIdx.x;
    int idx = blockIdx.x * 256 + t;
    int v = (idx < N_NODES + 1) ? g_rowptr[idx] : 0;
    sh[t] = v;
    __syncthreads();
#pragma unroll
    for (int off = 1; off < 256; off <<= 1) {
        int u = (t >= off) ? sh[t - off] : 0;
        __syncthreads();
        sh[t] += u;
        __syncthreads();
    }
    if (idx < N_NODES + 1) g_rowptr[idx] = sh[t];
    if (t == 255) g_bsum[blockIdx.x] = sh[255];
}

__global__ void k_scan3() {
    __shared__ int sh[256];
    int t = threadIdx.x;
    sh[t] = (t < (int)blockIdx.x) ? g_bsum[t] : 0;
    __syncthreads();
#pragma unroll
    for (int off = 128; off > 0; off >>= 1) {
        if (t < off) sh[t] += sh[t + off];
        __syncthreads();
    }
    int offset = sh[0];
    int idx = blockIdx.x * 256 + t;
    if (idx < N_NODES + 1) {
        int v = g_rowptr[idx] + offset;
        g_rowptr[idx] = v;
        if (idx < N_NODES) g_cursor[idx] = v;
    }
}

// ---------------- HMMA fp16 GEMM core: swizzled smem, cp.async 5-stage ----------
__device__ __forceinline__ void mma_f16(float* c, const uint32_t* a, const uint32_t* b) {
    asm("mma.sync.aligned.m16n8k16.row.col.f32.f16.f16.f32 "
        "{%0,%1,%2,%3}, {%4,%5,%6,%7}, {%8,%9}, {%0,%1,%2,%3};"
        : "+f"(c[0]), "+f"(c[1]), "+f"(c[2]), "+f"(c[3])
        : "r"(a[0]), "r"(a[1]), "r"(a[2]), "r"(a[3]), "r"(b[0]), "r"(b[1]));
}

#define LDSM4(r0, r1, r2, r3, addr)                                            \
    asm volatile("ldmatrix.sync.aligned.m8n8.x4.shared.b16 {%0,%1,%2,%3}, [%4];" \
                 : "=r"(r0), "=r"(r1), "=r"(r2), "=r"(r3) : "r"(addr))
#define CPA16(dst, src, n)                                                     \
    asm volatile("cp.async.cg.shared.global [%0], [%1], 16, %2;"               \
                 :: "r"(dst), "l"(src), "r"(n))
#define CP_COMMIT() asm volatile("cp.async.commit_group;" ::: "memory")

// stage layout (bytes): A@0, B@8192; stage=16384. 64B rows; swizzle c ^ ((r>>1)&3)
#define STG  16384
#define T_B  8192
#define NSTG 5

__device__ __forceinline__ void gemm_load_stage(
    uint32_t sb, const __half* __restrict__ A, const __half* __restrict__ B,
    int rowBase, int colBase, int M, int k0, int tid)
{
#pragma unroll
    for (int it = 0; it < 2; it++) {
        int ch = tid + it * 256;
        int r = ch >> 2, c = ch & 3;
        uint32_t so = (uint32_t)(r * 64 + ((c ^ ((r >> 1) & 3)) * 16));
        int gr = rowBase + r;
        int ok = (gr < M) ? 16 : 0;
        int grc = (gr < M) ? gr : (M - 1);
        CPA16(sb + so,       A + (size_t)grc * 256 + k0 + c * 8, ok);
        CPA16(sb + T_B + so, B + (size_t)(colBase + r) * 256 + k0 + c * 8, 16);
    }
}

__device__ __forceinline__ void gemm_core(
    const __half* __restrict__ A, const __half* __restrict__ B,
    __half* __restrict__ C, int M, int N, int bx, int by)
{
    extern __shared__ __align__(128) char dsm[];
    uint32_t sb = (uint32_t)__cvta_generic_to_shared(dsm);

    int tid = threadIdx.x;
    int lane = tid & 31, wid = tid >> 5;
    int rowBase = by * 128, colBase = bx * 128;
    int wm = (wid >> 2) * 64;
    int wn = (wid & 3) * 32;

    float acc[4][4][4];
#pragma unroll
    for (int mi = 0; mi < 4; mi++)
#pragma unroll
        for (int ni = 0; ni < 4; ni++)
#pragma unroll
            for (int q = 0; q < 4; q++) acc[mi][ni][q] = 0.f;

    uint32_t aRow[4], aS[4], bRow[2], bS[2];
    uint32_t kaBase = (lane & 16) ? 16u : 0u;
    uint32_t kbBase = (lane & 8) ? 16u : 0u;
    {
        int ra = (lane & 7) + ((lane & 8) ? 8 : 0);
#pragma unroll
        for (int mi = 0; mi < 4; mi++) {
            int r = wm + mi * 16 + ra;
            aRow[mi] = (uint32_t)(r * 64);
            aS[mi]   = (uint32_t)(((r >> 1) & 3) * 16);
        }
        int rb = (lane & 7) + ((lane & 16) ? 8 : 0);
#pragma unroll
        for (int p = 0; p < 2; p++) {
            int r = wn + p * 16 + rb;
            bRow[p] = (uint32_t)(r * 64);
            bS[p]   = (uint32_t)(((r >> 1) & 3) * 16);
        }
    }

    const int KT = 8;
    // prologue: fill 4 stages
#pragma unroll
    for (int s = 0; s < 4; s++) {
        gemm_load_stage(sb + (uint32_t)s * STG, A, B, rowBase, colBase, M,
                        s * 32, tid);
        CP_COMMIT();
    }

    for (int kt = 0; kt < KT; kt++) {
        uint32_t cur = sb + (uint32_t)(kt % NSTG) * STG;
        if (kt < KT - 4) {
            gemm_load_stage(sb + (uint32_t)((kt + 4) % NSTG) * STG,
                            A, B, rowBase, colBase, M, (kt + 4) * 32, tid);
            CP_COMMIT();
            asm volatile("cp.async.wait_group 4;" ::: "memory");
        } else if (kt == KT - 4) {
            asm volatile("cp.async.wait_group 3;" ::: "memory");
        } else if (kt == KT - 3) {
            asm volatile("cp.async.wait_group 2;" ::: "memory");
        } else if (kt == KT - 2) {
            asm volatile("cp.async.wait_group 1;" ::: "memory");
        } else {
            asm volatile("cp.async.wait_group 0;" ::: "memory");
        }
        __syncthreads();

#pragma unroll
        for (int ks = 0; ks < 2; ks++) {
            uint32_t kA = (uint32_t)(ks * 32) + kaBase;
            uint32_t kB = (uint32_t)(ks * 32) + kbBase;
            uint32_t bfr[8], af[4][4];
            LDSM4(bfr[0], bfr[1], bfr[2], bfr[3],
                  cur + T_B + bRow[0] + (kB ^ bS[0]));
            LDSM4(bfr[4], bfr[5], bfr[6], bfr[7],
                  cur + T_B + bRow[1] + (kB ^ bS[1]));
#pragma unroll
            for (int mi = 0; mi < 4; mi++)
                LDSM4(af[mi][0], af[mi][1], af[mi][2], af[mi][3],
                      cur + aRow[mi] + (kA ^ aS[mi]));
#pragma unroll
            for (int mi = 0; mi < 4; mi++)
#pragma unroll
                for (int ni = 0; ni < 4; ni++)
                    mma_f16(acc[mi][ni], af[mi], &bfr[ni * 2]);
        }
        if (kt + 1 < KT) __syncthreads();
    }

#pragma unroll
    for (int mi = 0; mi < 4; mi++) {
        int rr = rowBase + wm + mi * 16 + (lane >> 2);
#pragma unroll
        for (int ni = 0; ni < 4; ni++) {
            int cc = colBase + wn + ni * 8 + (lane & 3) * 2;
            if (rr < M)
                *(__half2*)&C[(size_t)rr * N + cc] =
                    __floats2half2_rn(acc[mi][ni][0], acc[mi][ni][1]);
            if (rr + 8 < M)
                *(__half2*)&C[(size_t)(rr + 8) * N + cc] =
                    __floats2half2_rn(acc[mi][ni][2], acc[mi][ni][3]);
        }
    }
}

// ---------------- GEMM1 with scatter slice appended ------------------------------
__global__ __launch_bounds__(256, 2)
void k_gemm1_scatter(const int* __restrict__ erow, const int* __restrict__ ecol,
                     const float* __restrict__ eval)
{
    gemm_core(g_Yh, g_W1T, g_H1, N_NODES, D_HID,
              blockIdx.x & 1, blockIdx.x >> 1);
    int base = blockIdx.x * EPB + threadIdx.x;
#pragma unroll
    for (int q = 0; q < EPB / 256; q++) {
        int i = base + q * 256;
        if (i < N_EDGES) {
            int r = erow[i];
            int p = atomicAdd(&g_cursor[r], 1);
            g_ecv[p] = make_int2(ecol[i], __float_as_int(eval[i]));
        }
    }
}

__global__ __launch_bounds__(256, 2)
void k_gemm2()
{
    gemm_core(g_H2, g_W2T, g_H3, N_NODES, D_OUT, 0, blockIdx.x);
}

// fp16 gather helper: 4 halves -> float4 accumulate
__device__ __forceinline__ void fma_h4(float4& acc, float v, uint2 raw) {
    float2 a01 = __half22float2(*(__half2*)&raw.x);
    float2 a23 = __half22float2(*(__half2*)&raw.y);
    acc.x += v * a01.x; acc.y += v * a01.y;
    acc.z += v * a23.x; acc.w += v * a23.y;
}

// ---------------- SpMM1: H2 = relu(spmm(H1fp16)) -> fp16, 4-wide -----------------
__global__ void k_spmm1() {
    int r = blockIdx.x * 4 + threadIdx.y;
    if (r >= N_NODES) return;
    int f4 = threadIdx.x * 4;               // 64 lanes x 4 feats = 256
    int e   = g_rowptr[r];
    int end = g_rowptr[r + 1];
    float4 acc = make_float4(0.f, 0.f, 0.f, 0.f);
    for (; e + 4 <= end; e += 4) {
        int2 cv0 = __ldg(&g_ecv[e]);
        int2 cv1 = __ldg(&g_ecv[e + 1]);
        int2 cv2 = __ldg(&g_ecv[e + 2]);
        int2 cv3 = __ldg(&g_ecv[e + 3]);
        uint2 x0 = __ldg((const uint2*)&g_H1[(size_t)cv0.x * D_HID + f4]);
        uint2 x1 = __ldg((const uint2*)&g_H1[(size_t)cv1.x * D_HID + f4]);
        uint2 x2 = __ldg((const uint2*)&g_H1[(size_t)cv2.x * D_HID + f4]);
        uint2 x3 = __ldg((const uint2*)&g_H1[(size_t)cv3.x * D_HID + f4]);
        fma_h4(acc, __int_as_float(cv0.y), x0);
        fma_h4(acc, __int_as_float(cv1.y), x1);
        fma_h4(acc, __int_as_float(cv2.y), x2);
        fma_h4(acc, __int_as_float(cv3.y), x3);
    }
    for (; e < end; e++) {
        int2 cv = __ldg(&g_ecv[e]);
        uint2 x = __ldg((const uint2*)&g_H1[(size_t)cv.x * D_HID + f4]);
        fma_h4(acc, __int_as_float(cv.y), x);
    }
    acc.x = fmaxf(acc.x, 0.f); acc.y = fmaxf(acc.y, 0.f);
    acc.z = fmaxf(acc.z, 0.f); acc.w = fmaxf(acc.w, 0.f);
    uint2 h;
    __half2 h01 = __floats2half2_rn(acc.x, acc.y);
    __half2 h23 = __floats2half2_rn(acc.z, acc.w);
    h.x = *(uint32_t*)&h01; h.y = *(uint32_t*)&h23;
    *(uint2*)&g_H2[(size_t)r * D_HID + f4] = h;
}

// ---------------- SpMM2: out = spmm(H3fp16), 4-wide -------------------------------
__global__ void k_spmm2(float* __restrict__ out) {
    int r = blockIdx.x * 8 + threadIdx.y;
    if (r >= N_NODES) return;
    int f4 = threadIdx.x * 4;               // 32 lanes x 4 feats = 128
    int e   = g_rowptr[r];
    int end = g_rowptr[r + 1];
    float4 acc = make_float4(0.f, 0.f, 0.f, 0.f);
    for (; e + 4 <= end; e += 4) {
        int2 cv0 = __ldg(&g_ecv[e]);
        int2 cv1 = __ldg(&g_ecv[e + 1]);
        int2 cv2 = __ldg(&g_ecv[e + 2]);
        int2 cv3 = __ldg(&g_ecv[e + 3]);
        uint2 x0 = __ldg((const uint2*)&g_H3[(size_t)cv0.x * D_OUT + f4]);
        uint2 x1 = __ldg((const uint2*)&g_H3[(size_t)cv1.x * D_OUT + f4]);
        uint2 x2 = __ldg((const uint2*)&g_H3[(size_t)cv2.x * D_OUT + f4]);
        uint2 x3 = __ldg((const uint2*)&g_H3[(size_t)cv3.x * D_OUT + f4]);
        fma_h4(acc, __int_as_float(cv0.y), x0);
        fma_h4(acc, __int_as_float(cv1.y), x1);
        fma_h4(acc, __int_as_float(cv2.y), x2);
        fma_h4(acc, __int_as_float(cv3.y), x3);
    }
    for (; e < end; e++) {
        int2 cv = __ldg(&g_ecv[e]);
        uint2 x = __ldg((const uint2*)&g_H3[(size_t)cv.x * D_OUT + f4]);
        fma_h4(acc, __int_as_float(cv.y), x);
    }
    *(float4*)&out[(size_t)r * D_OUT + f4] = acc;
}

// ---------------- launch -----------------------------------------------------------
extern "C" void kernel_launch(void* const* d_in, const int* in_sizes, int n_in,
                              void* d_out, int out_size) {
    const float* Y        = (const float*)d_in[0];
    const int*   edge_row = (const int*)d_in[1];
    const int*   edge_col = (const int*)d_in[2];
    const float* edge_val = (const float*)d_in[3];
    const float* W1       = (const float*)d_in[4];
    const float* W2       = (const float*)d_in[5];
    float*       out      = (float*)d_out;

    int *pRowptr;
    cudaGetSymbolAddress((void**)&pRowptr, g_rowptr);

    const int DSM = NSTG * STG;   // 81920 B
    cudaFuncSetAttribute(k_gemm1_scatter,
                         cudaFuncAttributeMaxDynamicSharedMemorySize, DSM);
    cudaFuncSetAttribute(k_gemm2,
                         cudaFuncAttributeMaxDynamicSharedMemorySize, DSM);

    cudaMemsetAsync(pRowptr, 0, (N_NODES + 1) * sizeof(int));
    k_init_all<<<HISTB + 256 + 128 + YSPB, 256>>>(edge_row, W1, W2, Y);
    k_scan1<<<196, 256>>>();
    k_scan3<<<196, 256>>>();
    k_gemm1_scatter<<<G1B, 256, DSM>>>(edge_row, edge_col, edge_val);
    {
        dim3 blk(64, 4);
        k_spmm1<<<(N_NODES + 3) / 4, blk>>>();
    }
    k_gemm2<<<GRID_M, 256, DSM>>>();
    {
        dim3 blk(32, 8);
        k_spmm2<<<(N_NODES + 7) / 8, blk>>>(out);
    }
}

// round 13
// speedup vs baseline: 1.3874x; 1.0160x over previous
#include <cuda_runtime.h>
#include <cuda_fp16.h>
#include <cstdint>

#define N_NODES 50000
#define N_EDGES 800000
#define D_IN    256
#define D_HID   256
#define D_OUT   128
#define HISTB   3125           // ceil(800000/256)
#define YSPB    12500          // 50000*256/4 float4 / 256 threads
#define NTILES  391            // ceil(50000/128)
#define GGRID   148            // persistent GEMM blocks (1/SM)

// ---------------- scratch ------------------------------------------------------
__device__ __half g_H1[(size_t)N_NODES * D_HID];
__device__ __half g_H2[(size_t)N_NODES * D_HID];
__device__ __half g_H3[(size_t)N_NODES * D_OUT];
__device__ __half g_Yh[(size_t)N_NODES * D_IN];
__device__ __half g_W1T[D_HID * D_IN];
__device__ __half g_W2T[D_OUT * D_HID];
__device__ int   g_rowptr[N_NODES + 1];
__device__ int   g_cursor[N_NODES];
__device__ int   g_bsum[256];
__device__ int2  g_ecv[N_EDGES];

// ---------------- K1: hist + W transposes (fp16) + Y convert -------------------
__global__ void k_init_all(const int* __restrict__ erow,
                           const float* __restrict__ W1,
                           const float* __restrict__ W2,
                           const float* __restrict__ Y) {
    int b = blockIdx.x;
    if (b < HISTB) {
        int i = b * 256 + threadIdx.x;
        if (i < N_EDGES) atomicAdd(&g_rowptr[erow[i] + 1], 1);
        return;
    }
    b -= HISTB;
    if (b < 256) {               // W1 [256][256] -> T fp16
        int i = b * 256 + threadIdx.x;
        int r = i >> 8, c = i & 255;
        g_W1T[(size_t)c * D_IN + r] = __float2half(W1[i]);
        return;
    }
    b -= 256;
    if (b < 128) {               // W2 [256][128] -> T fp16
        int i = b * 256 + threadIdx.x;
        int r = i >> 7, c = i & 127;
        g_W2T[(size_t)c * D_HID + r] = __float2half(W2[i]);
        return;
    }
    b -= 128;
    {                            // Y convert: 3.2M float4 chunks -> 4x fp16
        int j = b * 256 + threadIdx.x;
        float4 f = __ldg(((const float4*)Y) + j);
        uint2 h;
        __half2 h01 = __floats2half2_rn(f.x, f.y);
        __half2 h23 = __floats2half2_rn(f.z, f.w);
        h.x = *(uint32_t*)&h01; h.y = *(uint32_t*)&h23;
        ((uint2*)g_Yh)[j] = h;
    }
}

// ---------------- parallel scan (2 phases) --------------------------------------
__global__ void k_scan1() {
    __shared__ int sh[256];
    int t = threadIdx.x;
    int idx = blockIdx.x * 256 + t;
    int v = (idx < N_NODES + 1) ? g_rowptr[idx] : 0;
    sh[t] = v;
    __syncthreads();
#pragma unroll
    for (int off = 1; off < 256; off <<= 1) {
        int u = (t >= off) ? sh[t - off] : 0;
        __syncthreads();
        sh[t] += u;
        __syncthreads();
    }
    if (idx < N_NODES + 1) g_rowptr[idx] = sh[t];
    if (t == 255) g_bsum[blockIdx.x] = sh[255];
}

__global__ void k_scan3() {
    __shared__ int sh[256];
    int t = threadIdx.x;
    sh[t] = (t < (int)blockIdx.x) ? g_bsum[t] : 0;
    __syncthreads();
#pragma unroll
    for (int off = 128; off > 0; off >>= 1) {
        if (t < off) sh[t] += sh[t + off];
        __syncthreads();
    }
    int offset = sh[0];
    int idx = blockIdx.x * 256 + t;
    if (idx < N_NODES + 1) {
        int v = g_rowptr[idx] + offset;
        g_rowptr[idx] = v;
        if (idx < N_NODES) g_cursor[idx] = v;
    }
}

// ---------------- PTX helpers ----------------------------------------------------
__device__ __forceinline__ void mma_f16(float* c, const uint32_t* a, const uint32_t* b) {
    asm("mma.sync.aligned.m16n8k16.row.col.f32.f16.f16.f32 "
        "{%0,%1,%2,%3}, {%4,%5,%6,%7}, {%8,%9}, {%0,%1,%2,%3};"
        : "+f"(c[0]), "+f"(c[1]), "+f"(c[2]), "+f"(c[3])
        : "r"(a[0]), "r"(a[1]), "r"(a[2]), "r"(a[3]), "r"(b[0]), "r"(b[1]));
}

#define LDSM4(r0, r1, r2, r3, addr)                                            \
    asm volatile("ldmatrix.sync.aligned.m8n8.x4.shared.b16 {%0,%1,%2,%3}, [%4];" \
                 : "=r"(r0), "=r"(r1), "=r"(r2), "=r"(r3) : "r"(addr))
#define CPA16(dst, src, n)                                                     \
    asm volatile("cp.async.cg.shared.global [%0], [%1], 16, %2;"               \
                 :: "r"(dst), "l"(src), "r"(n))
#define CP_COMMIT() asm volatile("cp.async.commit_group;" ::: "memory")

#define SWZ(r, c) ((uint32_t)((r) * 64 + (((c) ^ (((r) >> 1) & 3)) * 16)))

// GEMM1 smem: B resident 8 slabs x 16KB @0; A ring 4 x 8KB @131072
#define B1SLAB 16384
#define A1OFF  131072
#define ASTG   8192
#define DSM1   (A1OFF + 4 * ASTG)   // 163840
// GEMM2 smem: B resident 8 slabs x 8KB @0; A ring 4 x 8KB @65536
#define B2SLAB 8192
#define A2OFF  65536
#define DSM2   (A2OFF + 4 * ASTG)   // 98304

// ---------------- GEMM1 persistent (N=256 resident W1) + scatter -----------------
__global__ __launch_bounds__(512, 1)
void k_gemm1_scatter(const int* __restrict__ erow, const int* __restrict__ ecol,
                     const float* __restrict__ eval)
{
    extern __shared__ __align__(128) char dsm[];
    uint32_t sb;
    {
        uint64_t t64 = (uint64_t)__cvta_generic_to_shared(dsm);
        sb = (uint32_t)t64;
    }
    uint32_t bB = sb, bA = sb + A1OFF;
    int tid = threadIdx.x, lane = tid & 31, wid = tid >> 5;
    int wm = (wid & 3) * 32;          // 4 x 32 = 128 M
    int wn = (wid >> 2) * 64;         // 4 x 64 = 256 N

    uint32_t aRow[2], aS[2], bRow[4], bS[4];
    uint32_t kaBase = (lane & 16) ? 16u : 0u;
    uint32_t kbBase = (lane & 8) ? 16u : 0u;
    {
        int ra = (lane & 7) + ((lane & 8) ? 8 : 0);
#pragma unroll
        for (int mi = 0; mi < 2; mi++) {
            int r = wm + mi * 16 + ra;
            aRow[mi] = (uint32_t)(r * 64);
            aS[mi]   = (uint32_t)(((r >> 1) & 3) * 16);
        }
        int rb = (lane & 7) + ((lane & 16) ? 8 : 0);
#pragma unroll
        for (int p = 0; p < 4; p++) {
            int r = wn + p * 16 + rb;
            bRow[p] = (uint32_t)(r * 64);
            bS[p]   = (uint32_t)(((r >> 1) & 3) * 16);
        }
    }

    bool first = true;
    for (int my = blockIdx.x; my < NTILES; my += GGRID) {
        int rowBase = my * 128;
        float acc[2][8][4];
#pragma unroll
        for (int mi = 0; mi < 2; mi++)
#pragma unroll
            for (int ni = 0; ni < 8; ni++)
#pragma unroll
                for (int q = 0; q < 4; q++) acc[mi][ni][q] = 0.f;

        // prologue: A stages 0..2 (+ B slabs 0..2 on first tile)
#pragma unroll
        for (int s = 0; s < 3; s++) {
            {
                int r = tid >> 2, c = tid & 3;
                int gr = rowBase + r;
                int ok = (gr < N_NODES) ? 16 : 0;
                int grc = (gr < N_NODES) ? gr : (N_NODES - 1);
                CPA16(bA + (uint32_t)s * ASTG + SWZ(r, c),
                      g_Yh + (size_t)grc * 256 + s * 32 + c * 8, ok);
            }
            if (first) {
#pragma unroll
                for (int it = 0; it < 2; it++) {
                    int ch = tid + it * 512;
                    int r = ch >> 2, c = ch & 3;
                    CPA16(bB + (uint32_t)s * B1SLAB + SWZ(r, c),
                          g_W1T + (size_t)r * 256 + s * 32 + c * 8, 16);
                }
            }
            CP_COMMIT();
        }

        for (int kt = 0; kt < 8; kt++) {
            uint32_t curA = bA + (uint32_t)(kt & 3) * ASTG;
            uint32_t curB = bB + (uint32_t)kt * B1SLAB;
            if (kt < 5) {
                int s = kt + 3;
                {
                    int r = tid >> 2, c = tid & 3;
                    int gr = rowBase + r;
                    int ok = (gr < N_NODES) ? 16 : 0;
                    int grc = (gr < N_NODES) ? gr : (N_NODES - 1);
                    CPA16(bA + (uint32_t)(s & 3) * ASTG + SWZ(r, c),
                          g_Yh + (size_t)grc * 256 + s * 32 + c * 8, ok);
                }
                if (first) {
#pragma unroll
                    for (int it = 0; it < 2; it++) {
                        int ch = tid + it * 512;
                        int r = ch >> 2, c = ch & 3;
                        CPA16(bB + (uint32_t)s * B1SLAB + SWZ(r, c),
                              g_W1T + (size_t)r * 256 + s * 32 + c * 8, 16);
                    }
                }
                CP_COMMIT();
                asm volatile("cp.async.wait_group 3;" ::: "memory");
            } else if (kt == 5) {
                asm volatile("cp.async.wait_group 2;" ::: "memory");
            } else if (kt == 6) {
                asm volatile("cp.async.wait_group 1;" ::: "memory");
            } else {
                asm volatile("cp.async.wait_group 0;" ::: "memory");
            }
            __syncthreads();

#pragma unroll
            for (int ks = 0; ks < 2; ks++) {
                uint32_t kA = (uint32_t)(ks * 32) + kaBase;
                uint32_t kB = (uint32_t)(ks * 32) + kbBase;
                uint32_t af[2][4], bf[4][4];
#pragma unroll
                for (int p = 0; p < 4; p++)
                    LDSM4(bf[p][0], bf[p][1], bf[p][2], bf[p][3],
                          curB + bRow[p] + (kB ^ bS[p]));
#pragma unroll
                for (int mi = 0; mi < 2; mi++)
                    LDSM4(af[mi][0], af[mi][1], af[mi][2], af[mi][3],
                          curA + aRow[mi] + (kA ^ aS[mi]));
#pragma unroll
                for (int mi = 0; mi < 2; mi++)
#pragma unroll
                    for (int p = 0; p < 4; p++) {
                        mma_f16(acc[mi][p * 2],     af[mi], &bf[p][0]);
                        mma_f16(acc[mi][p * 2 + 1], af[mi], &bf[p][2]);
                    }
            }
            __syncthreads();
        }

        // epilogue -> g_H1 (fp16), N = 256
#pragma unroll
        for (int mi = 0; mi < 2; mi++) {
            int rr = rowBase + wm + mi * 16 + (lane >> 2);
#pragma unroll
            for (int ni = 0; ni < 8; ni++) {
                int cc = wn + ni * 8 + (lane & 3) * 2;
                if (rr < N_NODES)
                    *(__half2*)&g_H1[(size_t)rr * 256 + cc] =
                        __floats2half2_rn(acc[mi][ni][0], acc[mi][ni][1]);
                if (rr + 8 < N_NODES)
                    *(__half2*)&g_H1[(size_t)(rr + 8) * 256 + cc] =
                        __floats2half2_rn(acc[mi][ni][2], acc[mi][ni][3]);
            }
        }
        first = false;
    }

    // scatter: grid-stride over edges
    for (int i = blockIdx.x * 512 + tid; i < N_EDGES; i += GGRID * 512) {
        int r = erow[i];
        int p = atomicAdd(&g_cursor[r], 1);
        g_ecv[p] = make_int2(ecol[i], __float_as_int(eval[i]));
    }
}

// ---------------- GEMM2 persistent (N=128 resident W2) ---------------------------
__global__ __launch_bounds__(512, 1)
void k_gemm2()
{
    extern __shared__ __align__(128) char dsm[];
    uint32_t sb;
    {
        uint64_t t64 = (uint64_t)__cvta_generic_to_shared(dsm);
        sb = (uint32_t)t64;
    }
    uint32_t bB = sb, bA = sb + A2OFF;
    int tid = threadIdx.x, lane = tid & 31, wid = tid >> 5;
    int wm = (wid & 3) * 32;          // 4 x 32 = 128 M
    int wn = (wid >> 2) * 32;         // 4 x 32 = 128 N

    uint32_t aRow[2], aS[2], bRow[2], bS[2];
    uint32_t kaBase = (lane & 16) ? 16u : 0u;
    uint32_t kbBase = (lane & 8) ? 16u : 0u;
    {
        int ra = (lane & 7) + ((lane & 8) ? 8 : 0);
#pragma unroll
        for (int mi = 0; mi < 2; mi++) {
            int r = wm + mi * 16 + ra;
            aRow[mi] = (uint32_t)(r * 64);
            aS[mi]   = (uint32_t)(((r >> 1) & 3) * 16);
        }
        int rb = (lane & 7) + ((lane & 16) ? 8 : 0);
#pragma unroll
        for (int p = 0; p < 2; p++) {
            int r = wn + p * 16 + rb;
            bRow[p] = (uint32_t)(r * 64);
            bS[p]   = (uint32_t)(((r >> 1) & 3) * 16);
        }
    }

    bool first = true;
    for (int my = blockIdx.x; my < NTILES; my += GGRID) {
        int rowBase = my * 128;
        float acc[2][4][4];
#pragma unroll
        for (int mi = 0; mi < 2; mi++)
#pragma unroll
            for (int ni = 0; ni < 4; ni++)
#pragma unroll
                for (int q = 0; q < 4; q++) acc[mi][ni][q] = 0.f;

#pragma unroll
        for (int s = 0; s < 3; s++) {
            {
                int r = tid >> 2, c = tid & 3;
                int gr = rowBase + r;
                int ok = (gr < N_NODES) ? 16 : 0;
                int grc = (gr < N_NODES) ? gr : (N_NODES - 1);
                CPA16(bA + (uint32_t)s * ASTG + SWZ(r, c),
                      g_H2 + (size_t)grc * 256 + s * 32 + c * 8, ok);
            }
            if (first) {
                int r = tid >> 2, c = tid & 3;   // 128 rows x 4 = 512 chunks
                CPA16(bB + (uint32_t)s * B2SLAB + SWZ(r, c),
                      g_W2T + (size_t)r * 256 + s * 32 + c * 8, 16);
            }
            CP_COMMIT();
        }

        for (int kt = 0; kt < 8; kt++) {
            uint32_t curA = bA + (uint32_t)(kt & 3) * ASTG;
            uint32_t curB = bB + (uint32_t)kt * B2SLAB;
            if (kt < 5) {
                int s = kt + 3;
                {
                    int r = tid >> 2, c = tid & 3;
                    int gr = rowBase + r;
                    int ok = (gr < N_NODES) ? 16 : 0;
                    int grc = (gr < N_NODES) ? gr : (N_NODES - 1);
                    CPA16(bA + (uint32_t)(s & 3) * ASTG + SWZ(r, c),
                          g_H2 + (size_t)grc * 256 + s * 32 + c * 8, ok);
                }
                if (first) {
                    int r = tid >> 2, c = tid & 3;
                    CPA16(bB + (uint32_t)s * B2SLAB + SWZ(r, c),
                          g_W2T + (size_t)r * 256 + s * 32 + c * 8, 16);
                }
                CP_COMMIT();
                asm volatile("cp.async.wait_group 3;" ::: "memory");
            } else if (kt == 5) {
                asm volatile("cp.async.wait_group 2;" ::: "memory");
            } else if (kt == 6) {
                asm volatile("cp.async.wait_group 1;" ::: "memory");
            } else {
                asm volatile("cp.async.wait_group 0;" ::: "memory");
            }
            __syncthreads();

#pragma unroll
            for (int ks = 0; ks < 2; ks++) {
                uint32_t kA = (uint32_t)(ks * 32) + kaBase;
                uint32_t kB = (uint32_t)(ks * 32) + kbBase;
                uint32_t af[2][4], bf[2][4];
#pragma unroll
                for (int p = 0; p < 2; p++)
                    LDSM4(bf[p][0], bf[p][1], bf[p][2], bf[p][3],
                          curB + bRow[p] + (kB ^ bS[p]));
#pragma unroll
                for (int mi = 0; mi < 2; mi++)
                    LDSM4(af[mi][0], af[mi][1], af[mi][2], af[mi][3],
                          curA + aRow[mi] + (kA ^ aS[mi]));
#pragma unroll
                for (int mi = 0; mi < 2; mi++)
#pragma unroll
                    for (int p = 0; p < 2; p++) {
                        mma_f16(acc[mi][p * 2],     af[mi], &bf[p][0]);
                        mma_f16(acc[mi][p * 2 + 1], af[mi], &bf[p][2]);
                    }
            }
            __syncthreads();
        }

        // epilogue -> g_H3 (fp16), N = 128
#pragma unroll
        for (int mi = 0; mi < 2; mi++) {
            int rr = rowBase + wm + mi * 16 + (lane >> 2);
#pragma unroll
            for (int ni = 0; ni < 4; ni++) {
                int cc = wn + ni * 8 + (lane & 3) * 2;
                if (rr < N_NODES)
                    *(__half2*)&g_H3[(size_t)rr * 128 + cc] =
                        __floats2half2_rn(acc[mi][ni][0], acc[mi][ni][1]);
                if (rr + 8 < N_NODES)
                    *(__half2*)&g_H3[(size_t)(rr + 8) * 128 + cc] =
                        __floats2half2_rn(acc[mi][ni][2], acc[mi][ni][3]);
            }
        }
        first = false;
    }
}

// fp16 gather helper: 4 halves -> float4 accumulate
__device__ __forceinline__ void fma_h4(float4& acc, float v, uint2 raw) {
    float2 a01 = __half22float2(*(__half2*)&raw.x);
    float2 a23 = __half22float2(*(__half2*)&raw.y);
    acc.x += v * a01.x; acc.y += v * a01.y;
    acc.z += v * a23.x; acc.w += v * a23.y;
}

// ---------------- SpMM1: H2 = relu(spmm(H1fp16)) -> fp16, 4-wide -----------------
__global__ void k_spmm1() {
    int r = blockIdx.x * 4 + threadIdx.y;
    if (r >= N_NODES) return;
    int f4 = threadIdx.x * 4;               // 64 lanes x 4 feats = 256
    int e   = g_rowptr[r];
    int end = g_rowptr[r + 1];
    float4 acc = make_float4(0.f, 0.f, 0.f, 0.f);
    for (; e + 4 <= end; e += 4) {
        int2 cv0 = __ldg(&g_ecv[e]);
        int2 cv1 = __ldg(&g_ecv[e + 1]);
        int2 cv2 = __ldg(&g_ecv[e + 2]);
        int2 cv3 = __ldg(&g_ecv[e + 3]);
        uint2 x0 = __ldg((const uint2*)&g_H1[(size_t)cv0.x * D_HID + f4]);
        uint2 x1 = __ldg((const uint2*)&g_H1[(size_t)cv1.x * D_HID + f4]);
        uint2 x2 = __ldg((const uint2*)&g_H1[(size_t)cv2.x * D_HID + f4]);
        uint2 x3 = __ldg((const uint2*)&g_H1[(size_t)cv3.x * D_HID + f4]);
        fma_h4(acc, __int_as_float(cv0.y), x0);
        fma_h4(acc, __int_as_float(cv1.y), x1);
        fma_h4(acc, __int_as_float(cv2.y), x2);
        fma_h4(acc, __int_as_float(cv3.y), x3);
    }
    for (; e < end; e++) {
        int2 cv = __ldg(&g_ecv[e]);
        uint2 x = __ldg((const uint2*)&g_H1[(size_t)cv.x * D_HID + f4]);
        fma_h4(acc, __int_as_float(cv.y), x);
    }
    acc.x = fmaxf(acc.x, 0.f); acc.y = fmaxf(acc.y, 0.f);
    acc.z = fmaxf(acc.z, 0.f); acc.w = fmaxf(acc.w, 0.f);
    uint2 h;
    __half2 h01 = __floats2half2_rn(acc.x, acc.y);
    __half2 h23 = __floats2half2_rn(acc.z, acc.w);
    h.x = *(uint32_t*)&h01; h.y = *(uint32_t*)&h23;
    *(uint2*)&g_H2[(size_t)r * D_HID + f4] = h;
}

// ---------------- SpMM2: out = spmm(H3fp16), 4-wide -------------------------------
__global__ void k_spmm2(float* __restrict__ out) {
    int r = blockIdx.x * 8 + threadIdx.y;
    if (r >= N_NODES) return;
    int f4 = threadIdx.x * 4;               // 32 lanes x 4 feats = 128
    int e   = g_rowptr[r];
    int end = g_rowptr[r + 1];
    float4 acc = make_float4(0.f, 0.f, 0.f, 0.f);
    for (; e + 4 <= end; e += 4) {
        int2 cv0 = __ldg(&g_ecv[e]);
        int2 cv1 = __ldg(&g_ecv[e + 1]);
        int2 cv2 = __ldg(&g_ecv[e + 2]);
        int2 cv3 = __ldg(&g_ecv[e + 3]);
        uint2 x0 = __ldg((const uint2*)&g_H3[(size_t)cv0.x * D_OUT + f4]);
        uint2 x1 = __ldg((const uint2*)&g_H3[(size_t)cv1.x * D_OUT + f4]);
        uint2 x2 = __ldg((const uint2*)&g_H3[(size_t)cv2.x * D_OUT + f4]);
        uint2 x3 = __ldg((const uint2*)&g_H3[(size_t)cv3.x * D_OUT + f4]);
        fma_h4(acc, __int_as_float(cv0.y), x0);
        fma_h4(acc, __int_as_float(cv1.y), x1);
        fma_h4(acc, __int_as_float(cv2.y), x2);
        fma_h4(acc, __int_as_float(cv3.y), x3);
    }
    for (; e < end; e++) {
        int2 cv = __ldg(&g_ecv[e]);
        uint2 x = __ldg((const uint2*)&g_H3[(size_t)cv.x * D_OUT + f4]);
        fma_h4(acc, __int_as_float(cv.y), x);
    }
    *(float4*)&out[(size_t)r * D_OUT + f4] = acc;
}

// ---------------- launch -----------------------------------------------------------
extern "C" void kernel_launch(void* const* d_in, const int* in_sizes, int n_in,
                              void* d_out, int out_size) {
    const float* Y        = (const float*)d_in[0];
    const int*   edge_row = (const int*)d_in[1];
    const int*   edge_col = (const int*)d_in[2];
    const float* edge_val = (const float*)d_in[3];
    const float* W1       = (const float*)d_in[4];
    const float* W2       = (const float*)d_in[5];
    float*       out      = (float*)d_out;

    int *pRowptr;
    cudaGetSymbolAddress((void**)&pRowptr, g_rowptr);

    cudaFuncSetAttribute(k_gemm1_scatter,
                         cudaFuncAttributeMaxDynamicSharedMemorySize, DSM1);
    cudaFuncSetAttribute(k_gemm2,
                         cudaFuncAttributeMaxDynamicSharedMemorySize, DSM2);

    cudaMemsetAsync(pRowptr, 0, (N_NODES + 1) * sizeof(int));
    k_init_all<<<HISTB + 256 + 128 + YSPB, 256>>>(edge_row, W1, W2, Y);
    k_scan1<<<196, 256>>>();
    k_scan3<<<196, 256>>>();
    k_gemm1_scatter<<<GGRID, 512, DSM1>>>(edge_row, edge_col, edge_val);
    {
        dim3 blk(64, 4);
        k_spmm1<<<(N_NODES + 3) / 4, blk>>>();
    }
    k_gemm2<<<GGRID, 512, DSM2>>>();
    {
        dim3 blk(32, 8);
        k_spmm2<<<(N_NODES + 7) / 8, blk>>>(out);
    }
}